// round 5
// baseline (speedup 1.0000x reference)
#include <cuda_runtime.h>

#define HID   128
#define NOUT  4096
#define NBLK  32
#define SLICE (NOUT / NBLK)      // 128 columns per block
#define NB1   256                // blocks for xW1 stage-1
#define ROWS1 256                // rows per block in stage-1 (NB1*ROWS1 = 65536)
#define EPT   256                // threads in persistent kernel

// ---- global scratch (static __device__ arrays: allowed, no allocation) ----
__device__ float              g_xw1_partial[NB1][HID];
__device__ unsigned long long g_slots[2][NBLK][HID];   // (tag<<32)|float_bits

__device__ __forceinline__ float clip01(float v) { return fminf(fmaxf(v, 0.f), 1.f); }

// Zero the tagged slots so graph replays never see stale tags.
__global__ void init_kernel() {
    int idx = blockIdx.x * blockDim.x + threadIdx.x;
    if (idx < 2 * NBLK * HID) (&g_slots[0][0][0])[idx] = 0ull;
}

// Stage 1 of xW1 = clip(x) @ W1 : each block reduces 256 rows -> partial[128]
__global__ void __launch_bounds__(HID) xw1_partial_kernel(
    const float* __restrict__ x, const float* __restrict__ W1)
{
    int b = blockIdx.x;
    int k = threadIdx.x;                       // 0..127 (output column)
    const float* W1p = W1 + (size_t)b * ROWS1 * HID + k;
    const float* xp  = x  + (size_t)b * ROWS1;
    float a0 = 0.f, a1 = 0.f, a2 = 0.f, a3 = 0.f;
#pragma unroll 8
    for (int r = 0; r < ROWS1; r += 4) {
        a0 = fmaf(clip01(xp[r + 0]), W1p[(size_t)(r + 0) * HID], a0);
        a1 = fmaf(clip01(xp[r + 1]), W1p[(size_t)(r + 1) * HID], a1);
        a2 = fmaf(clip01(xp[r + 2]), W1p[(size_t)(r + 2) * HID], a2);
        a3 = fmaf(clip01(xp[r + 3]), W1p[(size_t)(r + 3) * HID], a3);
    }
    g_xw1_partial[b][k] = (a0 + a1) + (a2 + a3);
}

// Persistent kernel: 32 co-resident blocks run all iterations.
extern __shared__ float sm_dyn[];
__global__ void __launch_bounds__(EPT, 1) ep_kernel(
    const float* __restrict__ W2,
    const float* __restrict__ b_h,
    const float* __restrict__ b_out,
    const float* __restrict__ h0,
    const float* __restrict__ o0,
    const int*   __restrict__ n_iter_p,
    const float* __restrict__ eps_p,
    float*       __restrict__ out)
{
    float* W2s  = sm_dyn;                 // [HID][SLICE]  row-major  (64 KB)
    float* W2sT = sm_dyn + HID * SLICE;   // [SLICE][HID]  transposed (64 KB)

    __shared__ float h_s[HID], mh_s[HID], vh_s[HID];
    __shared__ float rh_s[HID], ro_s[SLICE];
    __shared__ float bh_s[HID], xw1_s[HID];
    __shared__ float goP[2][SLICE], ghP[2][HID], gat2[2][HID];

    const int tid  = threadIdx.x;
    const int b    = blockIdx.x;
    const int lane = tid & 127;
    const int half = tid >> 7;

    int n_iter = *n_iter_p;
    if (n_iter <= 0 || n_iter > 1000000) {   // robustness if scalar arrives as fp32
        n_iter = (int)(*reinterpret_cast<const float*>(n_iter_p));
    }
    const float eps = *eps_p;

    // ---- load W2 slice into SMEM (both layouts) ----
    for (int idx = tid; idx < HID * SLICE / 4; idx += EPT) {
        int i  = idx >> 5;            // row 0..127
        int j4 = (idx & 31) << 2;     // col group
        const float4 w = *reinterpret_cast<const float4*>(
            W2 + (size_t)i * NOUT + (size_t)b * SLICE + j4);
        *reinterpret_cast<float4*>(W2s + i * SLICE + j4) = w;
        W2sT[(j4 + 0) * HID + i] = w.x;
        W2sT[(j4 + 1) * HID + i] = w.y;
        W2sT[(j4 + 2) * HID + i] = w.z;
        W2sT[(j4 + 3) * HID + i] = w.w;
    }

    // ---- stage 2 of xW1 (replicated per block, fixed order => identical) ----
    if (tid < HID) {
        float s0 = 0.f, s1 = 0.f, s2 = 0.f, s3 = 0.f;
#pragma unroll 8
        for (int p = 0; p < NB1; p += 4) {
            s0 += g_xw1_partial[p + 0][tid];
            s1 += g_xw1_partial[p + 1][tid];
            s2 += g_xw1_partial[p + 2][tid];
            s3 += g_xw1_partial[p + 3][tid];
        }
        xw1_s[tid] = (s0 + s1) + (s2 + s3);
        bh_s[tid]  = b_h[tid];
        h_s[tid]   = h0[tid];
        mh_s[tid]  = 0.f;
        vh_s[tid]  = 0.f;
    }

    float o_v = 0.f, mo = 0.f, vo = 0.f, bo = 0.f;
    if (tid < SLICE) {
        o_v = o0[(size_t)b * SLICE + tid];
        bo  = b_out[(size_t)b * SLICE + tid];
    }
    __syncthreads();

    const float B1 = 0.9f, B2 = 0.999f;
    const float OB1 = 1.0f - 0.9f, OB2 = 1.0f - 0.999f;
    const float AEPS = 1e-8f;
    float b1t = 1.f, b2t = 1.f;

    for (int t = 0; t < n_iter; ++t) {
        b1t *= B1; b2t *= B2;
        const float c1 = 1.f / (1.f - b1t);
        const float c2 = 1.f / (1.f - b2t);

        if (tid < HID)   rh_s[tid] = clip01(h_s[tid]);
        if (tid < SLICE) ro_s[tid] = clip01(o_v);
        __syncthreads();                                   // S1

        // pass A: (r_h @ W2)[j] partials  (thread=col j, loop over i-half)
        float a0 = 0.f, a1 = 0.f, a2 = 0.f, a3 = 0.f;
        {
            const float* wc = W2s + lane + (half << 6) * SLICE;
            const float* rh = rh_s + (half << 6);
#pragma unroll
            for (int k = 0; k < 64; k += 4) {
                a0 = fmaf(rh[k + 0], wc[(k + 0) * SLICE], a0);
                a1 = fmaf(rh[k + 1], wc[(k + 1) * SLICE], a1);
                a2 = fmaf(rh[k + 2], wc[(k + 2) * SLICE], a2);
                a3 = fmaf(rh[k + 3], wc[(k + 3) * SLICE], a3);
            }
        }
        goP[half][lane] = (a0 + a1) + (a2 + a3);

        // pass B: (W2 @ r_o)[i] partials  (thread=row i, loop over j-half, via W2sT)
        float d0 = 0.f, d1 = 0.f, d2 = 0.f, d3 = 0.f;
        {
            const float* wr = W2sT + lane + (half << 6) * HID;
            const float* ro = ro_s + (half << 6);
#pragma unroll
            for (int k = 0; k < 64; k += 4) {
                d0 = fmaf(ro[k + 0], wr[(k + 0) * HID], d0);
                d1 = fmaf(ro[k + 1], wr[(k + 1) * HID], d1);
                d2 = fmaf(ro[k + 2], wr[(k + 2) * HID], d2);
                d3 = fmaf(ro[k + 3], wr[(k + 3) * HID], d3);
            }
        }
        ghP[half][lane] = (d0 + d1) + (d2 + d3);
        __syncthreads();                                   // S2

        if (tid < SLICE) {
            // o Adam update (block-local, overlaps the cross-block exchange)
            float gsum = goP[0][tid] + goP[1][tid];
            float ro   = ro_s[tid];
            float mask = (o_v >= 0.f && o_v <= 1.f) ? 1.f : 0.f;
            float g    = mask * (ro - bo - gsum);
            mo  = B1 * mo + OB1 * g;
            vo  = B2 * vo + OB2 * g * g;
            o_v -= eps * (mo * c1) / (sqrtf(vo * c2) + AEPS);
        }
        if (tid < HID) {
            // publish this block's W2@r_o partial with iteration tag
            float part = ghP[0][tid] + ghP[1][tid];
            unsigned long long pk =
                ((unsigned long long)(unsigned)(t + 1) << 32) |
                (unsigned long long)__float_as_uint(part);
            __stcg(&g_slots[t & 1][b][tid], pk);
        }

        // gather all NBLK partials (tag-polled, deterministic order)
        {
            const unsigned long long* base = &g_slots[t & 1][half * (NBLK / 2)][lane];
            const unsigned tagv = (unsigned)(t + 1);
            unsigned long long v[NBLK / 2];
#pragma unroll
            for (int k = 0; k < NBLK / 2; k++) v[k] = __ldcg(base + (size_t)k * HID);
            for (;;) {
                bool again = false;
#pragma unroll
                for (int k = 0; k < NBLK / 2; k++) {
                    if ((unsigned)(v[k] >> 32) != tagv) {
                        v[k] = __ldcg(base + (size_t)k * HID);
                        if ((unsigned)(v[k] >> 32) != tagv) again = true;
                    }
                }
                if (!again) break;
            }
            float s = 0.f;
#pragma unroll
            for (int k = 0; k < NBLK / 2; k++)
                s += __uint_as_float((unsigned)(v[k] & 0xffffffffu));
            gat2[half][lane] = s;
        }
        __syncthreads();                                   // S3

        if (tid < HID) {
            // replicated h Adam update
            float S    = gat2[0][tid] + gat2[1][tid];
            float h    = h_s[tid];
            float mask = (h >= 0.f && h <= 1.f) ? 1.f : 0.f;
            float g    = mask * (rh_s[tid] - bh_s[tid] - xw1_s[tid] - S);
            float m    = B1 * mh_s[tid] + OB1 * g;
            float v2   = B2 * vh_s[tid] + OB2 * g * g;
            mh_s[tid] = m;
            vh_s[tid] = v2;
            h_s[tid]  = h - eps * (m * c1) / (sqrtf(v2 * c2) + AEPS);
        }
        __syncthreads();                                   // end-of-iter
    }

    if (tid < SLICE) out[(size_t)b * SLICE + tid] = o_v;
}

extern "C" void kernel_launch(void* const* d_in, const int* in_sizes, int n_in,
                              void* d_out, int out_size)
{
    (void)in_sizes; (void)n_in; (void)out_size;
    const float* x    = (const float*)d_in[0];
    const float* W1   = (const float*)d_in[1];
    const float* W2   = (const float*)d_in[2];
    // d_in[3] = b_in (unused by the reference dynamics)
    const float* b_h  = (const float*)d_in[4];
    const float* b_o  = (const float*)d_in[5];
    const float* h0   = (const float*)d_in[6];
    const float* o0   = (const float*)d_in[7];
    const int*   nit  = (const int*)d_in[8];
    const float* eps  = (const float*)d_in[9];
    float* out = (float*)d_out;

    static const size_t DYN_SMEM = (size_t)2 * HID * SLICE * sizeof(float); // 128 KB
    cudaFuncSetAttribute(ep_kernel, cudaFuncAttributeMaxDynamicSharedMemorySize,
                         (int)DYN_SMEM);

    init_kernel<<<32, 256>>>();
    xw1_partial_kernel<<<NB1, HID>>>(x, W1);
    ep_kernel<<<NBLK, EPT, DYN_SMEM>>>(W2, b_h, b_o, h0, o0, nit, eps, out);
}

// round 7
// speedup vs baseline: 1.6689x; 1.6689x over previous
#include <cuda_runtime.h>

#define HID   128
#define NOUT  4096
#define NBLK  32
#define SLICE (NOUT / NBLK)      // 128 columns per block
#define NB1   256                // blocks for xW1 stage-1
#define ROWS1 256                // rows per block in stage-1
#define EPT   256                // threads in persistent kernel
#define RPAD  132                // padded row stride (floats) for redA

// ---- global scratch ----
__device__ float              g_xw1_partial[NB1][HID];
__device__ unsigned long long g_slots[2][NBLK][HID];   // (tag<<32)|float_bits

__device__ __forceinline__ float clip01(float v) { return fminf(fmaxf(v, 0.f), 1.f); }

// Stage 1 of xW1 = clip(x) @ W1 ; also zeroes the exchange slots (replay safety)
__global__ void __launch_bounds__(HID) xw1_partial_kernel(
    const float* __restrict__ x, const float* __restrict__ W1)
{
    int b = blockIdx.x;
    int k = threadIdx.x;                       // 0..127
    if (b < 64)  // 64 blocks * 128 threads = 8192 = 2*NBLK*HID slots
        (&g_slots[0][0][0])[b * HID + k] = 0ull;

    const float* W1p = W1 + (size_t)b * ROWS1 * HID + k;
    const float* xp  = x  + (size_t)b * ROWS1;
    float a0 = 0.f, a1 = 0.f, a2 = 0.f, a3 = 0.f;
#pragma unroll 8
    for (int r = 0; r < ROWS1; r += 4) {
        a0 = fmaf(clip01(xp[r + 0]), W1p[(size_t)(r + 0) * HID], a0);
        a1 = fmaf(clip01(xp[r + 1]), W1p[(size_t)(r + 1) * HID], a1);
        a2 = fmaf(clip01(xp[r + 2]), W1p[(size_t)(r + 2) * HID], a2);
        a3 = fmaf(clip01(xp[r + 3]), W1p[(size_t)(r + 3) * HID], a3);
    }
    g_xw1_partial[b][k] = (a0 + a1) + (a2 + a3);
}

// Persistent kernel: 32 co-resident blocks, W2 slice register-resident.
__global__ void __launch_bounds__(EPT, 1) ep_kernel(
    const float* __restrict__ W2,
    const float* __restrict__ b_h,
    const float* __restrict__ b_out,
    const float* __restrict__ h0,
    const float* __restrict__ o0,
    const int*   __restrict__ n_iter_p,
    const float* __restrict__ eps_p,
    float*       __restrict__ out)
{
    __shared__ float redA[16][RPAD];                       // pass-A partials
    __shared__ __align__(16) float rh_s[HID];
    __shared__ __align__(16) float ro_s[SLICE];

    const int tid = threadIdx.x;
    const int b   = blockIdx.x;
    const int it  = tid >> 4;      // 0..15 : row tile  (rows it*8 .. +8)
    const int jt  = tid & 15;      // 0..15 : col tile  (cols jt*8 .. +8)

    int n_iter = *n_iter_p;
    if (n_iter <= 0 || n_iter > 1000000)
        n_iter = (int)(*reinterpret_cast<const float*>(n_iter_p));
    const float eps = *eps_p;

    // ---- load this thread's 8x8 W2 tile into registers ----
    float4 w4[8][2];
#pragma unroll
    for (int r = 0; r < 8; r++) {
        const float4* p = reinterpret_cast<const float4*>(
            W2 + (size_t)(it * 8 + r) * NOUT + (size_t)b * SLICE + jt * 8);
        w4[r][0] = p[0];
        w4[r][1] = p[1];
    }

    // ---- state init (warp-specialized ownership) ----
    float o_v = 0.f, mo = 0.f, vo = 0.f, bo = 0.f;          // tid < 128
    float h_v = 0.f, mh = 0.f, vh = 0.f, bh_r = 0.f, xw1_r = 0.f; // tid >= 128
    if (tid < SLICE) {
        o_v = o0[(size_t)b * SLICE + tid];
        bo  = b_out[(size_t)b * SLICE + tid];
        ro_s[tid] = clip01(o_v);
    } else {
        int i = tid - 128;
        float s0 = 0.f, s1 = 0.f, s2 = 0.f, s3 = 0.f;
#pragma unroll 8
        for (int p = 0; p < NB1; p += 4) {
            s0 += g_xw1_partial[p + 0][i];
            s1 += g_xw1_partial[p + 1][i];
            s2 += g_xw1_partial[p + 2][i];
            s3 += g_xw1_partial[p + 3][i];
        }
        xw1_r = (s0 + s1) + (s2 + s3);
        bh_r  = b_h[i];
        h_v   = h0[i];
        rh_s[i] = clip01(h_v);
    }
    __syncthreads();

    const float B1 = 0.9f, B2 = 0.999f;
    const float OB1 = 1.0f - 0.9f, OB2 = 1.0f - 0.999f;
    const float AEPS = 1e-8f;
    float b1t = 1.f, b2t = 1.f;

    for (int t = 0; t < n_iter; ++t) {
        b1t *= B1; b2t *= B2;
        const float c1 = 1.f / (1.f - b1t);
        const float c2 = 1.f / (1.f - b2t);
        const unsigned tagv = (unsigned)(t + 1);

        // ===== pass B: ghPart[i] = sum_j W2[i,j]*ro[j]  (per-warp complete) =====
        {
            const float4 r0 = *reinterpret_cast<const float4*>(ro_s + jt * 8);
            const float4 r1 = *reinterpret_cast<const float4*>(ro_s + jt * 8 + 4);
            float accB[8];
#pragma unroll
            for (int r = 0; r < 8; r++) {
                float a = w4[r][0].x * r0.x;
                a = fmaf(w4[r][0].y, r0.y, a);
                a = fmaf(w4[r][0].z, r0.z, a);
                a = fmaf(w4[r][0].w, r0.w, a);
                a = fmaf(w4[r][1].x, r1.x, a);
                a = fmaf(w4[r][1].y, r1.y, a);
                a = fmaf(w4[r][1].z, r1.z, a);
                accB[r] = fmaf(w4[r][1].w, r1.w, a);
            }
            // butterfly over the 16-lane jt-group (intra-warp, no barrier)
#pragma unroll
            for (int m = 1; m < 16; m <<= 1) {
#pragma unroll
                for (int r = 0; r < 8; r++)
                    accB[r] += __shfl_xor_sync(0xffffffffu, accB[r], m);
            }
            // lanes s<8 of each group publish row i = it*8 + s immediately
            int s = tid & 15;
            if (s < 8) {
                int i = it * 8 + s;
                float pv = accB[0];
#pragma unroll
                for (int r = 1; r < 8; r++) if (r == s) pv = accB[r];
                unsigned long long pk =
                    ((unsigned long long)tagv << 32) |
                    (unsigned long long)__float_as_uint(pv);
                __stcg(&g_slots[t & 1][b][i], pk);
            }
        }

        // ===== pass A: goPart[it][j] = sum_{r} rh[it*8+r]*W2[.,j] =====
        {
            const float4 q0 = *reinterpret_cast<const float4*>(rh_s + it * 8);
            const float4 q1 = *reinterpret_cast<const float4*>(rh_s + it * 8 + 4);
            float rh[8] = {q0.x, q0.y, q0.z, q0.w, q1.x, q1.y, q1.z, q1.w};
            float a0 = 0.f, a1 = 0.f, a2 = 0.f, a3 = 0.f;
            float a4 = 0.f, a5 = 0.f, a6 = 0.f, a7 = 0.f;
#pragma unroll
            for (int r = 0; r < 8; r++) {
                a0 = fmaf(rh[r], w4[r][0].x, a0);
                a1 = fmaf(rh[r], w4[r][0].y, a1);
                a2 = fmaf(rh[r], w4[r][0].z, a2);
                a3 = fmaf(rh[r], w4[r][0].w, a3);
                a4 = fmaf(rh[r], w4[r][1].x, a4);
                a5 = fmaf(rh[r], w4[r][1].y, a5);
                a6 = fmaf(rh[r], w4[r][1].z, a6);
                a7 = fmaf(rh[r], w4[r][1].w, a7);
            }
            *reinterpret_cast<float4*>(&redA[it][jt * 8])     = make_float4(a0, a1, a2, a3);
            *reinterpret_cast<float4*>(&redA[it][jt * 8 + 4]) = make_float4(a4, a5, a6, a7);
        }
        __syncthreads();                                   // S2

        if (tid < SLICE) {
            // ----- o path: reduce pass A over it, Adam update -----
            float g0 = 0.f, g1 = 0.f, g2 = 0.f, g3 = 0.f;
#pragma unroll
            for (int k = 0; k < 16; k += 4) {
                g0 += redA[k + 0][tid];
                g1 += redA[k + 1][tid];
                g2 += redA[k + 2][tid];
                g3 += redA[k + 3][tid];
            }
            float gsum = (g0 + g1) + (g2 + g3);
            float ro   = ro_s[tid];
            float mask = (o_v >= 0.f && o_v <= 1.f) ? 1.f : 0.f;
            float g    = mask * (ro - bo - gsum);
            mo  = B1 * mo + OB1 * g;
            vo  = B2 * vo + OB2 * g * g;
            o_v -= eps * (mo * c1) / (sqrtf(vo * c2) + AEPS);
            ro_s[tid] = clip01(o_v);
        } else {
            // ----- h path: gather all NBLK partials, replicated Adam update -----
            int i = tid - 128;
            const unsigned long long* sl = &g_slots[t & 1][0][i];
            float S = 0.f;
#pragma unroll
            for (int bb = 0; bb < 2; bb++) {
                unsigned long long v[16];
#pragma unroll
                for (int k = 0; k < 16; k++)
                    v[k] = __ldcg(sl + (size_t)(bb * 16 + k) * HID);
                for (;;) {
                    bool again = false;
#pragma unroll
                    for (int k = 0; k < 16; k++) {
                        if ((unsigned)(v[k] >> 32) != tagv) {
                            v[k] = __ldcg(sl + (size_t)(bb * 16 + k) * HID);
                            if ((unsigned)(v[k] >> 32) != tagv) again = true;
                        }
                    }
                    if (!again) break;
                }
#pragma unroll
                for (int k = 0; k < 16; k++)
                    S += __uint_as_float((unsigned)(v[k] & 0xffffffffu));
            }
            float rh   = rh_s[i];
            float mask = (h_v >= 0.f && h_v <= 1.f) ? 1.f : 0.f;
            float g    = mask * (rh - bh_r - xw1_r - S);
            mh  = B1 * mh + OB1 * g;
            vh  = B2 * vh + OB2 * g * g;
            h_v -= eps * (mh * c1) / (sqrtf(vh * c2) + AEPS);
            rh_s[i] = clip01(h_v);
        }
        __syncthreads();                                   // S3
    }

    if (tid < SLICE) out[(size_t)b * SLICE + tid] = o_v;
}

extern "C" void kernel_launch(void* const* d_in, const int* in_sizes, int n_in,
                              void* d_out, int out_size)
{
    (void)in_sizes; (void)n_in; (void)out_size;
    const float* x    = (const float*)d_in[0];
    const float* W1   = (const float*)d_in[1];
    const float* W2   = (const float*)d_in[2];
    // d_in[3] = b_in (unused by the reference dynamics)
    const float* b_h  = (const float*)d_in[4];
    const float* b_o  = (const float*)d_in[5];
    const float* h0   = (const float*)d_in[6];
    const float* o0   = (const float*)d_in[7];
    const int*   nit  = (const int*)d_in[8];
    const float* eps  = (const float*)d_in[9];
    float* out = (float*)d_out;

    xw1_partial_kernel<<<NB1, HID>>>(x, W1);
    ep_kernel<<<NBLK, EPT>>>(W2, b_h, b_o, h0, o0, nit, eps, out);
}

// round 9
// speedup vs baseline: 3.0101x; 1.8036x over previous
#include <cuda_runtime.h>
#include <cstdint>

#define HID    128
#define NOUT   4096
#define NBLK   16                 // one 16-CTA cluster
#define SLICE  (NOUT / NBLK)      // 256 columns per CTA
#define NB1    256                // blocks for xW1 stage-1
#define ROWS1  256                // rows per block in stage-1
#define EPT    512                // threads in persistent kernel
#define RPITCH (SLICE + 4)        // padded redA pitch (floats)

// ---- global scratch ----
__device__ float g_xw1_partial[NB1][HID];

__device__ __forceinline__ float clip01(float v) { return fminf(fmaxf(v, 0.f), 1.f); }

__device__ __forceinline__ uint32_t smem_u32(const void* p) {
    return (uint32_t)__cvta_generic_to_shared(p);
}
__device__ __forceinline__ uint32_t mapa_u32(uint32_t addr, int rank) {
    uint32_t r;
    asm("mapa.shared::cluster.u32 %0, %1, %2;" : "=r"(r) : "r"(addr), "r"(rank));
    return r;
}
__device__ __forceinline__ unsigned long long pk2(float lo, float hi) {
    unsigned long long r;
    asm("mov.b64 %0, {%1, %2};" : "=l"(r) : "f"(lo), "f"(hi));
    return r;
}
__device__ __forceinline__ void upk2(unsigned long long v, float& lo, float& hi) {
    asm("mov.b64 {%0, %1}, %2;" : "=f"(lo), "=f"(hi) : "l"(v));
}
__device__ __forceinline__ unsigned long long fma2(unsigned long long a,
                                                   unsigned long long b,
                                                   unsigned long long c) {
    unsigned long long d;
    asm("fma.rn.f32x2 %0, %1, %2, %3;" : "=l"(d) : "l"(a), "l"(b), "l"(c));
    return d;
}
__device__ __forceinline__ void st_async_cluster(uint32_t raddr, uint32_t val,
                                                 uint32_t rmbar) {
    asm volatile(
        "st.async.shared::cluster.mbarrier::complete_tx::bytes.u32 [%0], %1, [%2];"
        :: "r"(raddr), "r"(val), "r"(rmbar) : "memory");
}
__device__ __forceinline__ void mbar_init(uint32_t mbar, uint32_t cnt) {
    asm volatile("mbarrier.init.shared.b64 [%0], %1;" :: "r"(mbar), "r"(cnt) : "memory");
}
__device__ __forceinline__ void mbar_expect_tx(uint32_t mbar, uint32_t bytes) {
    asm volatile("mbarrier.arrive.expect_tx.shared.b64 _, [%0], %1;"
                 :: "r"(mbar), "r"(bytes) : "memory");
}
__device__ __forceinline__ void mbar_wait(uint32_t mbar, uint32_t parity) {
    asm volatile(
        "{\n\t.reg .pred P1;\n\t"
        "WAIT_%=: \n\t"
        "mbarrier.try_wait.parity.acquire.cta.shared::cta.b64 P1, [%0], %1, 0x989680;\n\t"
        "@P1 bra.uni DONE_%=;\n\t"
        "bra.uni WAIT_%=;\n\t"
        "DONE_%=: \n\t}"
        :: "r"(mbar), "r"(parity) : "memory");
}
__device__ __forceinline__ void cluster_sync() {
    asm volatile("barrier.cluster.arrive.aligned;" ::: "memory");
    asm volatile("barrier.cluster.wait.aligned;" ::: "memory");
}

// Stage 1 of xW1 = clip(x) @ W1
__global__ void __launch_bounds__(HID) xw1_partial_kernel(
    const float* __restrict__ x, const float* __restrict__ W1)
{
    int b = blockIdx.x;
    int k = threadIdx.x;
    const float* W1p = W1 + (size_t)b * ROWS1 * HID + k;
    const float* xp  = x  + (size_t)b * ROWS1;
    float a0 = 0.f, a1 = 0.f, a2 = 0.f, a3 = 0.f;
#pragma unroll 8
    for (int r = 0; r < ROWS1; r += 4) {
        a0 = fmaf(clip01(xp[r + 0]), W1p[(size_t)(r + 0) * HID], a0);
        a1 = fmaf(clip01(xp[r + 1]), W1p[(size_t)(r + 1) * HID], a1);
        a2 = fmaf(clip01(xp[r + 2]), W1p[(size_t)(r + 2) * HID], a2);
        a3 = fmaf(clip01(xp[r + 3]), W1p[(size_t)(r + 3) * HID], a3);
    }
    g_xw1_partial[b][k] = (a0 + a1) + (a2 + a3);
}

// Persistent cluster kernel: 16 CTAs, register-resident W2, DSMEM exchange.
__global__ void __launch_bounds__(EPT, 1) ep_kernel(
    const float* __restrict__ W2,
    const float* __restrict__ b_h,
    const float* __restrict__ b_out,
    const float* __restrict__ h0,
    const float* __restrict__ o0,
    const int*   __restrict__ n_iter_p,
    const float* __restrict__ eps_p,
    float*       __restrict__ out)
{
    __shared__ __align__(16) float redA[16][RPITCH];      // pass-A partials
    __shared__ __align__(16) float rh_s[HID];
    __shared__ __align__(16) float ro_s[SLICE];
    __shared__ __align__(16) float buf[2][NBLK][HID];     // exchange buffers
    __shared__ __align__(8)  unsigned long long mbar[2];

    const int tid  = threadIdx.x;
    const int b    = blockIdx.x;          // == cluster rank (grid == 1 cluster)
    const int wid  = tid >> 5;            // 0..15 : row tile (rows wid*8..+8)
    const int lane = tid & 31;            // 0..31 : col tile (cols lane*8..+8)

    const uint32_t buf_u32  = smem_u32(&buf[0][0][0]);
    const uint32_t mbar_u32 = smem_u32(&mbar[0]);

    int n_iter = *n_iter_p;
    if (n_iter <= 0 || n_iter > 1000000)
        n_iter = (int)(*reinterpret_cast<const float*>(n_iter_p));
    const float eps = *eps_p;

    if (tid == 0) { mbar_init(mbar_u32, 1); mbar_init(mbar_u32 + 8, 1); }

    // ---- load + pack this thread's 8x8 W2 tile (j-packed f32x2 pairs) ----
    unsigned long long wp[8][4];
#pragma unroll
    for (int r = 0; r < 8; r++) {
        const float4* p = reinterpret_cast<const float4*>(
            W2 + (size_t)(wid * 8 + r) * NOUT + (size_t)b * SLICE + lane * 8);
        float4 u = p[0], v = p[1];
        wp[r][0] = pk2(u.x, u.y);
        wp[r][1] = pk2(u.z, u.w);
        wp[r][2] = pk2(v.x, v.y);
        wp[r][3] = pk2(v.z, v.w);
    }

    // ---- state init (warp-specialized ownership) ----
    float o_v = 0.f, mo = 0.f, vo = 0.f, bo = 0.f;                 // tid < 256
    float h_v = 0.f, mh = 0.f, vh = 0.f, bh_r = 0.f, xw1_r = 0.f;  // tid in [256,384)
    if (tid < SLICE) {
        o_v = o0[(size_t)b * SLICE + tid];
        bo  = b_out[(size_t)b * SLICE + tid];
        ro_s[tid] = clip01(o_v);
    } else if (tid < SLICE + HID) {
        int i = tid - SLICE;
        float s0 = 0.f, s1 = 0.f, s2 = 0.f, s3 = 0.f;
#pragma unroll 8
        for (int p = 0; p < NB1; p += 4) {
            s0 += g_xw1_partial[p + 0][i];
            s1 += g_xw1_partial[p + 1][i];
            s2 += g_xw1_partial[p + 2][i];
            s3 += g_xw1_partial[p + 3][i];
        }
        xw1_r = (s0 + s1) + (s2 + s3);
        bh_r  = b_h[i];
        h_v   = h0[i];
        rh_s[i] = clip01(h_v);
    }
    __syncthreads();
    cluster_sync();    // all CTAs' mbarriers + state visible before any st.async

    const float B1 = 0.9f, B2 = 0.999f;
    const float OB1 = 1.0f - 0.9f, OB2 = 1.0f - 0.999f;
    const float AEPS = 1e-8f;
    float b1t = 1.f, b2t = 1.f;

    for (int t = 0; t < n_iter; ++t) {
        b1t *= B1; b2t *= B2;
        const float c1 = 1.f / (1.f - b1t);
        const float c2 = 1.f / (1.f - b2t);
        const int p      = t & 1;
        const int parity = (t >> 1) & 1;

        if (tid == 0) mbar_expect_tx(mbar_u32 + p * 8, NBLK * HID * 4);

        // ===== pass B: row partials, full-warp folded butterfly, st.async push =====
        {
            const unsigned long long* roq =
                reinterpret_cast<const unsigned long long*>(ro_s) + lane * 4;
            unsigned long long q0 = roq[0], q1 = roq[1], q2 = roq[2], q3 = roq[3];
            float rv[8];
#pragma unroll
            for (int r = 0; r < 8; r++) {
                unsigned long long acc = fma2(wp[r][0], q0, 0ull);
                acc = fma2(wp[r][1], q1, acc);
                acc = fma2(wp[r][2], q2, acc);
                acc = fma2(wp[r][3], q3, acc);
                float lo, hi; upk2(acc, lo, hi);
                rv[r] = lo + hi;
            }
            // folded butterfly: 16 shfl + 7 sel -> one row-sum per lane
#pragma unroll
            for (int r = 0; r < 8; r++) rv[r] += __shfl_xor_sync(0xffffffffu, rv[r], 16);
            float v4[4];
#pragma unroll
            for (int j = 0; j < 4; j++) v4[j] = (lane & 16) ? rv[j + 4] : rv[j];
#pragma unroll
            for (int j = 0; j < 4; j++) v4[j] += __shfl_xor_sync(0xffffffffu, v4[j], 8);
            float v2[2];
#pragma unroll
            for (int j = 0; j < 2; j++) v2[j] = (lane & 8) ? v4[j + 2] : v4[j];
#pragma unroll
            for (int j = 0; j < 2; j++) v2[j] += __shfl_xor_sync(0xffffffffu, v2[j], 4);
            float v1 = (lane & 4) ? v2[1] : v2[0];
            v1 += __shfl_xor_sync(0xffffffffu, v1, 2);
            v1 += __shfl_xor_sync(0xffffffffu, v1, 1);

            int r   = (((lane >> 4) & 1) << 2) | (((lane >> 3) & 1) << 1) | ((lane >> 2) & 1);
            int row = wid * 8 + r;
            uint32_t lofs = buf_u32 + (uint32_t)(((p * NBLK + b) * HID + row) * 4);
            uint32_t lmb  = mbar_u32 + p * 8;
            uint32_t vb   = __float_as_uint(v1);
#pragma unroll
            for (int g = 0; g < 4; g++) {
                int peer = ((lane & 3) << 2) | g;
                st_async_cluster(mapa_u32(lofs, peer), vb, mapa_u32(lmb, peer));
            }
        }

        // ===== pass A: col partials via packed FFMA2, store to redA =====
        {
            unsigned long long pa0 = 0ull, pa1 = 0ull, pa2 = 0ull, pa3 = 0ull;
#pragma unroll
            for (int r = 0; r < 8; r++) {
                float hv = rh_s[wid * 8 + r];            // broadcast LDS
                unsigned long long hp = pk2(hv, hv);
                pa0 = fma2(hp, wp[r][0], pa0);
                pa1 = fma2(hp, wp[r][1], pa1);
                pa2 = fma2(hp, wp[r][2], pa2);
                pa3 = fma2(hp, wp[r][3], pa3);
            }
            ulonglong2* dst = reinterpret_cast<ulonglong2*>(&redA[wid][lane * 8]);
            dst[0] = make_ulonglong2(pa0, pa1);
            dst[1] = make_ulonglong2(pa2, pa3);
        }
        __syncthreads();                                   // S2

        if (tid < SLICE) {
            // ----- o path: reduce pass A over the 16 row-tiles, Adam -----
            float g0 = 0.f, g1 = 0.f, g2 = 0.f, g3 = 0.f;
#pragma unroll
            for (int k = 0; k < 16; k += 4) {
                g0 += redA[k + 0][tid];
                g1 += redA[k + 1][tid];
                g2 += redA[k + 2][tid];
                g3 += redA[k + 3][tid];
            }
            float gsum = (g0 + g1) + (g2 + g3);
            float ro   = clip01(o_v);
            float mask = (o_v >= 0.f && o_v <= 1.f) ? 1.f : 0.f;
            float g    = mask * (ro - bo - gsum);
            mo  = B1 * mo + OB1 * g;
            vo  = B2 * vo + OB2 * g * g;
            o_v -= eps * (mo * c1) / (sqrtf(vo * c2) + AEPS);
            ro_s[tid] = clip01(o_v);
        } else if (tid < SLICE + HID) {
            // ----- h path: DSMEM-gathered sum, replicated Adam -----
            int i = tid - SLICE;
            mbar_wait(mbar_u32 + p * 8, (uint32_t)parity);
            float s0 = 0.f, s1 = 0.f, s2 = 0.f, s3 = 0.f;
#pragma unroll
            for (int s = 0; s < NBLK; s += 4) {
                s0 += buf[p][s + 0][i];
                s1 += buf[p][s + 1][i];
                s2 += buf[p][s + 2][i];
                s3 += buf[p][s + 3][i];
            }
            float S    = (s0 + s1) + (s2 + s3);
            float rh   = rh_s[i];
            float mask = (h_v >= 0.f && h_v <= 1.f) ? 1.f : 0.f;
            float g    = mask * (rh - bh_r - xw1_r - S);
            mh  = B1 * mh + OB1 * g;
            vh  = B2 * vh + OB2 * g * g;
            h_v -= eps * (mh * c1) / (sqrtf(vh * c2) + AEPS);
            rh_s[i] = clip01(h_v);
        }
        __syncthreads();                                   // S3
    }

    if (tid < SLICE) out[(size_t)b * SLICE + tid] = o_v;
    cluster_sync();
}

extern "C" void kernel_launch(void* const* d_in, const int* in_sizes, int n_in,
                              void* d_out, int out_size)
{
    (void)in_sizes; (void)n_in; (void)out_size;
    const float* x    = (const float*)d_in[0];
    const float* W1   = (const float*)d_in[1];
    const float* W2   = (const float*)d_in[2];
    // d_in[3] = b_in (unused by the reference dynamics)
    const float* b_h  = (const float*)d_in[4];
    const float* b_o  = (const float*)d_in[5];
    const float* h0   = (const float*)d_in[6];
    const float* o0   = (const float*)d_in[7];
    const int*   nit  = (const int*)d_in[8];
    const float* eps  = (const float*)d_in[9];
    float* out = (float*)d_out;

    xw1_partial_kernel<<<NB1, HID>>>(x, W1);

    cudaFuncSetAttribute(ep_kernel, cudaFuncAttributeNonPortableClusterSizeAllowed, 1);

    cudaLaunchConfig_t cfg = {};
    cfg.gridDim  = dim3(NBLK, 1, 1);
    cfg.blockDim = dim3(EPT, 1, 1);
    cfg.dynamicSmemBytes = 0;
    cfg.stream = 0;
    cudaLaunchAttribute at[1];
    at[0].id = cudaLaunchAttributeClusterDimension;
    at[0].val.clusterDim.x = NBLK;
    at[0].val.clusterDim.y = 1;
    at[0].val.clusterDim.z = 1;
    cfg.attrs = at;
    cfg.numAttrs = 1;
    cudaLaunchKernelEx(&cfg, ep_kernel, W2, b_h, b_o, h0, o0, nit, eps, out);
}